// round 1
// baseline (speedup 1.0000x reference)
#include <cuda_runtime.h>
#include <math.h>

#define N_NODES 50000
#define N_EDGES 600000
#define N_GRAPHS 64
#define HID 128
#define IN_DIM 16
#define OUT_DIM 256
#define N_LAYERS 3
#define STRIDE 132   // padded row stride (floats) for smem tiles

// ---------------- device scratch (static, no allocation) ----------------
__device__ float d_h[N_NODES * HID];
__device__ float d_A[N_NODES * HID];     // h@W1a + b1   (also reused for emb_out result)
__device__ float d_B[N_NODES * HID];     // h@W1b
__device__ float d_T[N_NODES * HID];     // node-update hidden
__device__ float d_magg[N_NODES * HID];  // edge message aggregation
__device__ float d_cagg[N_NODES * 3];
__device__ float d_coord[N_NODES * 3];
__device__ float d_deg[N_NODES];
__device__ float d_gsum[N_GRAPHS * HID];
__device__ float d_gcnt[N_GRAPHS];

__device__ __forceinline__ float silu_f(float x) {
    return x / (1.0f + __expf(-x));
}

// ---------------- init: zero accumulators, copy coord ----------------
__global__ void init_kernel(const float* __restrict__ coord_in) {
    int idx = blockIdx.x * blockDim.x + threadIdx.x;
    if (idx < N_NODES * HID) d_magg[idx] = 0.0f;
    if (idx < N_NODES * 3) { d_cagg[idx] = 0.0f; d_coord[idx] = coord_in[idx]; }
    if (idx < N_NODES) d_deg[idx] = 0.0f;
    if (idx < N_GRAPHS * HID) d_gsum[idx] = 0.0f;
    if (idx < N_GRAPHS) d_gcnt[idx] = 0.0f;
}

__global__ void deg_kernel(const int* __restrict__ row) {
    int e = blockIdx.x * blockDim.x + threadIdx.x;
    if (e < N_EDGES) atomicAdd(&d_deg[row[e]], 1.0f);
}

// ---------------- embedding in: h = x @ W + b  (K=16) ----------------
__global__ void emb_in_kernel(const float* __restrict__ x,
                              const float* __restrict__ w,
                              const float* __restrict__ b) {
    int idx = blockIdx.x * blockDim.x + threadIdx.x;
    if (idx >= N_NODES * HID) return;
    int n = idx >> 7, ch = idx & 127;
    float acc = b[ch];
#pragma unroll
    for (int k = 0; k < IN_DIM; k++) acc += x[n * IN_DIM + k] * w[k * HID + ch];
    d_h[idx] = acc;
}

// ---------------- micro GEMM: 8 rows x 4 cols per thread ----------------
// Xs: smem [64][STRIDE] row-major, Ws: smem [128][128] row-major
__device__ __forceinline__ void mgemm(const float* __restrict__ Xs,
                                      const float* __restrict__ Ws,
                                      int ty, int tx, float acc[8][4]) {
#pragma unroll
    for (int i = 0; i < 8; i++) { acc[i][0] = 0.f; acc[i][1] = 0.f; acc[i][2] = 0.f; acc[i][3] = 0.f; }
    const float* xb = &Xs[(ty * 8) * STRIDE];
#pragma unroll 4
    for (int k = 0; k < 128; k++) {
        float4 w = *reinterpret_cast<const float4*>(&Ws[(k << 7) + (tx << 2)]);
#pragma unroll
        for (int i = 0; i < 8; i++) {
            float xv = xb[i * STRIDE + k];
            acc[i][0] += xv * w.x; acc[i][1] += xv * w.y;
            acc[i][2] += xv * w.z; acc[i][3] += xv * w.w;
        }
    }
}

// ---------------- generic node GEMM: Y = op(X@W (+bias) (+Y)) ----------------
// mode bits: 1=BIAS, 2=ACC (add old Y), 4=SILU (after ACC), 8=CLEARX (zero X after load)
#define GM_BIAS 1
#define GM_ACC 2
#define GM_SILU 4
#define GM_CLEARX 8
__global__ void __launch_bounds__(256, 2)
gemm128_kernel(float* __restrict__ X, const float* __restrict__ W,
               const float* __restrict__ bias, float* __restrict__ Y, int mode) {
    extern __shared__ float sm[];
    float* Ws = sm;             // 16384 floats
    float* Xs = sm + 16384;     // 64*STRIDE = 8448
    float* bs = Xs + 64 * STRIDE;  // 128
    int tid = threadIdx.x;
    for (int i = tid; i < 4096; i += 256)
        reinterpret_cast<float4*>(Ws)[i] = reinterpret_cast<const float4*>(W)[i];
    if (tid < 128) bs[tid] = (mode & GM_BIAS) ? bias[tid] : 0.0f;
    __syncthreads();

    int ty = tid >> 5, tx = tid & 31;
    int ntiles = (N_NODES + 63) / 64;
    for (int tile = blockIdx.x; tile < ntiles; tile += gridDim.x) {
        int r0 = tile * 64;
#pragma unroll
        for (int i = 0; i < 32; i++) {
            int idx = i * 256 + tid;
            int r = idx >> 7, k = idx & 127;
            int gr = r0 + r;
            float v = 0.0f;
            if (gr < N_NODES) {
                v = X[gr * HID + k];
                if (mode & GM_CLEARX) X[gr * HID + k] = 0.0f;
            }
            Xs[r * STRIDE + k] = v;
        }
        __syncthreads();
        float acc[8][4];
        mgemm(Xs, Ws, ty, tx, acc);
        float4 b4 = *reinterpret_cast<const float4*>(&bs[tx * 4]);
#pragma unroll
        for (int i = 0; i < 8; i++) {
            int gr = r0 + ty * 8 + i;
            if (gr < N_NODES) {
                float4 res;
                res.x = acc[i][0] + b4.x; res.y = acc[i][1] + b4.y;
                res.z = acc[i][2] + b4.z; res.w = acc[i][3] + b4.w;
                float* yp = &Y[gr * HID + tx * 4];
                if (mode & GM_ACC) {
                    float4 old = *reinterpret_cast<float4*>(yp);
                    res.x += old.x; res.y += old.y; res.z += old.z; res.w += old.w;
                }
                if (mode & GM_SILU) {
                    res.x = silu_f(res.x); res.y = silu_f(res.y);
                    res.z = silu_f(res.z); res.w = silu_f(res.w);
                }
                *reinterpret_cast<float4*>(yp) = res;
            }
        }
        __syncthreads();
    }
}

// ---------------- edge kernel: per-64-edge tile fused edge MLP ----------------
__global__ void __launch_bounds__(256, 1)
edge_kernel(const int* __restrict__ row, const int* __restrict__ col,
            const float* __restrict__ ea,
            const float* __restrict__ W2, const float* __restrict__ b2,
            const float* __restrict__ Wc1, const float* __restrict__ bc1,
            const float* __restrict__ wc2,
            const float* __restrict__ wr, const float* __restrict__ we) {
    extern __shared__ float sm[];
    float* W2s = sm;                    // 16384
    float* Wc1s = W2s + 16384;          // 16384
    float* tS = Wc1s + 16384;           // 64*STRIDE
    float* mS = tS + 64 * STRIDE;       // 64*STRIDE
    float* b2s = mS + 64 * STRIDE;      // 128
    float* bc1s = b2s + 128;
    float* wc2s = bc1s + 128;
    float* wrs = wc2s + 128;
    float* wes = wrs + 128;
    float* diffs = wes + 128;           // 64*3
    int* rows_s = (int*)(diffs + 192);  // 64

    int tid = threadIdx.x;
    for (int i = tid; i < 4096; i += 256) {
        reinterpret_cast<float4*>(W2s)[i] = reinterpret_cast<const float4*>(W2)[i];
        reinterpret_cast<float4*>(Wc1s)[i] = reinterpret_cast<const float4*>(Wc1)[i];
    }
    if (tid < 128) {
        b2s[tid] = b2[tid]; bc1s[tid] = bc1[tid]; wc2s[tid] = wc2[tid];
        wrs[tid] = wr[tid]; wes[tid] = we[tid];
    }
    __syncthreads();

    int ty = tid >> 5, tx = tid & 31;
    int e_loc = tid >> 2, q = tid & 3;
    int ntiles = (N_EDGES + 63) / 64;

    for (int tile = blockIdx.x; tile < ntiles; tile += gridDim.x) {
        int e0 = tile * 64;
        int e = e0 + e_loc;
        // ---- Phase A: gather pre-activation, silu -> tS ----
        if (e < N_EDGES) {
            int r = row[e], c = col[e];
            float dx = d_coord[r * 3 + 0] - d_coord[c * 3 + 0];
            float dy = d_coord[r * 3 + 1] - d_coord[c * 3 + 1];
            float dz = d_coord[r * 3 + 2] - d_coord[c * 3 + 2];
            float radial = dx * dx + dy * dy + dz * dz;
            float eav = ea[e];
            if (q == 0) {
                rows_s[e_loc] = r;
                diffs[e_loc * 3 + 0] = dx; diffs[e_loc * 3 + 1] = dy; diffs[e_loc * 3 + 2] = dz;
            }
#pragma unroll
            for (int jj = 0; jj < 8; jj++) {
                int ch = q * 32 + jj * 4;
                float4 av = *reinterpret_cast<const float4*>(&d_A[r * HID + ch]);
                float4 bv = *reinterpret_cast<const float4*>(&d_B[c * HID + ch]);
                float4 w1 = *reinterpret_cast<const float4*>(&wrs[ch]);
                float4 w2v = *reinterpret_cast<const float4*>(&wes[ch]);
                float4 tv;
                tv.x = silu_f(av.x + bv.x + radial * w1.x + eav * w2v.x);
                tv.y = silu_f(av.y + bv.y + radial * w1.y + eav * w2v.y);
                tv.z = silu_f(av.z + bv.z + radial * w1.z + eav * w2v.z);
                tv.w = silu_f(av.w + bv.w + radial * w1.w + eav * w2v.w);
                *reinterpret_cast<float4*>(&tS[e_loc * STRIDE + ch]) = tv;
            }
        } else {
#pragma unroll
            for (int jj = 0; jj < 8; jj++) {
                int ch = q * 32 + jj * 4;
                *reinterpret_cast<float4*>(&tS[e_loc * STRIDE + ch]) = make_float4(0.f, 0.f, 0.f, 0.f);
            }
            if (q == 0) rows_s[e_loc] = 0;
        }
        __syncthreads();

        // ---- Phase B: m = silu(t @ W2 + b2) -> mS ----
        {
            float acc[8][4];
            mgemm(tS, W2s, ty, tx, acc);
            float4 b4 = *reinterpret_cast<const float4*>(&b2s[tx * 4]);
#pragma unroll
            for (int i = 0; i < 8; i++) {
                float4 mv;
                mv.x = silu_f(acc[i][0] + b4.x); mv.y = silu_f(acc[i][1] + b4.y);
                mv.z = silu_f(acc[i][2] + b4.z); mv.w = silu_f(acc[i][3] + b4.w);
                *reinterpret_cast<float4*>(&mS[(ty * 8 + i) * STRIDE + tx * 4]) = mv;
            }
        }
        __syncthreads();

        // ---- Phase B2: scatter magg ----
#pragma unroll
        for (int i = 0; i < 32; i++) {
            int idx = i * 256 + tid;
            int el = idx >> 7, ch = idx & 127;
            if (e0 + el < N_EDGES)
                atomicAdd(&d_magg[rows_s[el] * HID + ch], mS[el * STRIDE + ch]);
        }

        // ---- Phase C: cw = silu(m @ Wc1 + bc1) . wc2 ; scatter coord agg ----
        {
            float acc[8][4];
            mgemm(mS, Wc1s, ty, tx, acc);
            float4 bb = *reinterpret_cast<const float4*>(&bc1s[tx * 4]);
            float4 wv = *reinterpret_cast<const float4*>(&wc2s[tx * 4]);
            float part[8];
#pragma unroll
            for (int i = 0; i < 8; i++) {
                part[i] = silu_f(acc[i][0] + bb.x) * wv.x + silu_f(acc[i][1] + bb.y) * wv.y +
                          silu_f(acc[i][2] + bb.z) * wv.z + silu_f(acc[i][3] + bb.w) * wv.w;
            }
#pragma unroll
            for (int off = 16; off > 0; off >>= 1) {
#pragma unroll
                for (int i = 0; i < 8; i++)
                    part[i] += __shfl_xor_sync(0xffffffff, part[i], off);
            }
            if (tx < 8) {
                int el = ty * 8 + tx;
                if (e0 + el < N_EDGES) {
                    float cw = 0.0f;
#pragma unroll
                    for (int i = 0; i < 8; i++) if (tx == i) cw = part[i];
                    int r = rows_s[el];
                    atomicAdd(&d_cagg[r * 3 + 0], diffs[el * 3 + 0] * cw);
                    atomicAdd(&d_cagg[r * 3 + 1], diffs[el * 3 + 1] * cw);
                    atomicAdd(&d_cagg[r * 3 + 2], diffs[el * 3 + 2] * cw);
                }
            }
        }
        __syncthreads();
    }
}

// ---------------- coord update (and clear cagg) ----------------
__global__ void coord_kernel() {
    int n = blockIdx.x * blockDim.x + threadIdx.x;
    if (n < N_NODES) {
        float inv = 1.0f / fmaxf(d_deg[n], 1.0f);
#pragma unroll
        for (int dd = 0; dd < 3; dd++) {
            d_coord[n * 3 + dd] += d_cagg[n * 3 + dd] * inv;
            d_cagg[n * 3 + dd] = 0.0f;
        }
    }
}

// ---------------- global mean pool (batch is sorted) ----------------
__global__ void pool_kernel(const int* __restrict__ batch) {
    int n0 = blockIdx.x * 512;
    int ch = threadIdx.x;  // 128 threads
    if (n0 >= N_NODES) return;
    int nend = min(n0 + 512, N_NODES);
    int cur = batch[n0];
    float acc = 0.0f, cnt = 0.0f;
    for (int n = n0; n < nend; n++) {
        int g = batch[n];
        if (g != cur) {
            atomicAdd(&d_gsum[cur * HID + ch], acc);
            if (ch == 0) atomicAdd(&d_gcnt[cur], cnt);
            acc = 0.0f; cnt = 0.0f; cur = g;
        }
        acc += d_A[n * HID + ch];
        cnt += 1.0f;
    }
    atomicAdd(&d_gsum[cur * HID + ch], acc);
    if (ch == 0) atomicAdd(&d_gcnt[cur], cnt);
}

// ---------------- final fc: out = (gsum/gcnt) @ fc_w + fc_b ----------------
__global__ void fc_kernel(const float* __restrict__ fcw, const float* __restrict__ fcb,
                          float* __restrict__ out) {
    int g = blockIdx.x;
    int ch = threadIdx.x;  // 256
    float inv = 1.0f / fmaxf(d_gcnt[g], 1.0f);
    float acc = fcb[ch];
    for (int k = 0; k < HID; k++)
        acc += d_gsum[g * HID + k] * inv * fcw[k * OUT_DIM + ch];
    out[g * OUT_DIM + ch] = acc;
}

// ---------------- launch ----------------
#define GEMM_SMEM ((16384 + 64 * STRIDE + 128) * 4)
#define EDGE_SMEM ((16384 * 2 + 2 * 64 * STRIDE + 5 * 128 + 192) * 4 + 64 * 4)
#define GRID_G 592
#define GRID_E 148

extern "C" void kernel_launch(void* const* d_in, const int* in_sizes, int n_in,
                              void* d_out, int out_size) {
    const float* x = (const float*)d_in[0];
    const int* eidx = (const int*)d_in[1];
    const float* coord = (const float*)d_in[2];
    const float* ea = (const float*)d_in[3];
    const int* batch = (const int*)d_in[4];
    const float* emb_in_w = (const float*)d_in[5];
    const float* emb_in_b = (const float*)d_in[6];
    const float* edge_w1 = (const float*)d_in[7];
    const float* edge_b1 = (const float*)d_in[8];
    const float* edge_w2 = (const float*)d_in[9];
    const float* edge_b2 = (const float*)d_in[10];
    const float* node_w1 = (const float*)d_in[11];
    const float* node_b1 = (const float*)d_in[12];
    const float* node_w2 = (const float*)d_in[13];
    const float* node_b2 = (const float*)d_in[14];
    const float* coord_w1 = (const float*)d_in[15];
    const float* coord_b1 = (const float*)d_in[16];
    const float* coord_w2 = (const float*)d_in[17];
    const float* emb_out_w = (const float*)d_in[18];
    const float* emb_out_b = (const float*)d_in[19];
    const float* fc_w = (const float*)d_in[20];
    const float* fc_b = (const float*)d_in[21];
    float* out = (float*)d_out;

    const int* row = eidx;
    const int* col = eidx + N_EDGES;

    float *ph, *pA, *pB, *pT, *pmagg;
    cudaGetSymbolAddress((void**)&ph, d_h);
    cudaGetSymbolAddress((void**)&pA, d_A);
    cudaGetSymbolAddress((void**)&pB, d_B);
    cudaGetSymbolAddress((void**)&pT, d_T);
    cudaGetSymbolAddress((void**)&pmagg, d_magg);

    cudaFuncSetAttribute(edge_kernel, cudaFuncAttributeMaxDynamicSharedMemorySize, EDGE_SMEM);
    cudaFuncSetAttribute(gemm128_kernel, cudaFuncAttributeMaxDynamicSharedMemorySize, GEMM_SMEM);

    init_kernel<<<(N_NODES * HID + 255) / 256, 256>>>(coord);
    deg_kernel<<<(N_EDGES + 255) / 256, 256>>>(row);
    emb_in_kernel<<<(N_NODES * HID + 255) / 256, 256>>>(x, emb_in_w, emb_in_b);

    for (int l = 0; l < N_LAYERS; l++) {
        const float* W1 = edge_w1 + l * 258 * HID;
        // pre-projections: A = h@W1a + b1 ; B = h@W1b
        gemm128_kernel<<<GRID_G, 256, GEMM_SMEM>>>(ph, W1, edge_b1 + l * HID, pA, GM_BIAS);
        gemm128_kernel<<<GRID_G, 256, GEMM_SMEM>>>(ph, W1 + 128 * HID, nullptr, pB, 0);
        // fused edge MLP + aggregation
        edge_kernel<<<GRID_E, 256, EDGE_SMEM>>>(row, col, ea,
            edge_w2 + l * HID * HID, edge_b2 + l * HID,
            coord_w1 + l * HID * HID, coord_b1 + l * HID, coord_w2 + l * HID,
            W1 + 256 * HID, W1 + 257 * HID);
        // coord update
        coord_kernel<<<(N_NODES + 255) / 256, 256>>>();
        // node update: T = silu(h@nW1a + magg@nW1b + nb1); h += T@nW2 + nb2
        gemm128_kernel<<<GRID_G, 256, GEMM_SMEM>>>(ph, node_w1 + l * 256 * HID,
                                                   node_b1 + l * HID, pT, GM_BIAS);
        gemm128_kernel<<<GRID_G, 256, GEMM_SMEM>>>(pmagg, node_w1 + l * 256 * HID + 128 * HID,
                                                   nullptr, pT, GM_ACC | GM_SILU | GM_CLEARX);
        gemm128_kernel<<<GRID_G, 256, GEMM_SMEM>>>(pT, node_w2 + l * HID * HID,
                                                   node_b2 + l * HID, ph, GM_BIAS | GM_ACC);
    }

    // output embedding -> d_A
    gemm128_kernel<<<GRID_G, 256, GEMM_SMEM>>>(ph, emb_out_w, emb_out_b, pA, GM_BIAS);
    pool_kernel<<<(N_NODES + 511) / 512, 128>>>(batch);
    fc_kernel<<<N_GRAPHS, 256>>>(fc_w, fc_b, out);
}